// round 16
// baseline (speedup 1.0000x reference)
#include <cuda_runtime.h>
#include <cstdint>

// Problem constants (fixed by the reference).
#define BB 32
#define TT 4096
#define DD 128
#define CHUNK 32
#define CC (TT / CHUNK)        // 128 chunks per batch
#define NCH (BB * CC)          // 4096 chunks
#define NAGG (NCH * DD)        // 524288 (chunk, channel) slots

#define GRID_A 296             // 2 blocks/SM
#define KPB 14                 // chunks per block (296*14 >= 4096)

#define NDB 8                  // channels per passBC block
#define SP 129                 // padded chunk stride (bank-conflict break)

// Scratch (static device memory — no allocations). Transposed layout
// [(b*DD+d)*CC + c] so pass BC's scan loads are coalesced. has-flag in .y
// (y == 0 => no observation; real times are > 0, cumsum of dt >= 0.1).
__device__ float2 g_fwd2[NAGG];            // per-chunk last-obs  (x, t|0)  4 MB
__device__ float2 g_bwd2[NAGG];            // per-chunk first-obs (x, t|0)  4 MB
__device__ unsigned char g_headb[NAGG];    // head length (rows before 1st obs)
__device__ unsigned char g_tailb[NAGG];    // tail length (rows after last obs)

// ---------------------------------------------------------------------------
// cp.async helpers
// ---------------------------------------------------------------------------
__device__ __forceinline__ void cpa16(void* dst_smem, const void* src) {
    unsigned d = (unsigned)__cvta_generic_to_shared(dst_smem);
    asm volatile("cp.async.cg.shared.global [%0], [%1], 16;" :: "r"(d), "l"(src));
}
__device__ __forceinline__ void cpa_commit() {
    asm volatile("cp.async.commit_group;");
}
__device__ __forceinline__ void cpa_wait1() {
    asm volatile("cp.async.wait_group 1;" ::: "memory");
}

// ---------------------------------------------------------------------------
// Per-channel worker: ballot-derived last/next observation indices, shuffle
// gather, branchless interpolation. Lane 31 / lane 0 emit chunk aggregates.
// Non-interior (head/tail) rows emit t_j into out so pass BC's repair is a
// same-address read-modify-write (no separate t re-read).
// ---------------------------------------------------------------------------
__device__ __forceinline__ float do_ch(float vj, float tj, int mch,
                                       unsigned bits, unsigned lmle, unsigned lmge,
                                       int lane, int agg) {
    int li = 31 - __clz(bits & lmle);        // last obs <= row, or -1
    int ni = __clz(__brev(bits & lmge));     // first obs >= row, or 32
    float xl = __shfl_sync(0xffffffffu, vj, li);   // idx taken mod 32 by HW
    float tl = __shfl_sync(0xffffffffu, tj, li);
    float xn = __shfl_sync(0xffffffffu, vj, ni);
    float tn = __shfl_sync(0xffffffffu, tj, ni);

    if (lane == 31) {
        g_fwd2[agg] = make_float2(xl, li >= 0 ? tl : 0.f);
        g_tailb[agg] = (unsigned char)(li < 0 ? 0 : 31 - li);
    }
    if (lane == 0) {
        g_bwd2[agg] = make_float2(xn, ni < 32 ? tn : 0.f);
        g_headb[agg] = (unsigned char)ni;    // 0..32 (32 = empty chunk)
    }

    float itp = __fdividef(fmaf(xl, tn - tj, xn * (tj - tl)), tn - tl);
    bool interior = (li >= 0) && (ni < 32);  // head/tail rows fixed by pass BC
    return mch ? vj : (interior ? itp : tj);
}

// ---------------------------------------------------------------------------
// Pass A: persistent double-buffered cp.async pipeline. Dyn smem 112 KB,
// 2 blocks/SM. Non-interior rows emit t_j into out.
// ---------------------------------------------------------------------------
__global__ __launch_bounds__(256) void passA(const float4* __restrict__ v,
                                             const float4* __restrict__ t,
                                             const int4* __restrict__ m,
                                             float4* __restrict__ out) {
    extern __shared__ float4 dsm[];
    float4* sout = dsm + 6144;

    int tid = threadIdx.x;
    int base = blockIdx.x * KPB;
    int n = NCH - base; if (n > KPB) n = KPB;
    if (n <= 0) return;

    int lane = tid & 31, w = tid >> 5;
    unsigned lmle, lmge;
    asm("mov.u32 %0, %%lanemask_le;" : "=r"(lmle));
    asm("mov.u32 %0, %%lanemask_ge;" : "=r"(lmge));

    auto issue = [&](int chunk, int stg) {
        const float4* gv = v + chunk * 1024;
        const float4* gt = t + chunk * 1024;
        const int4*   gm = m + chunk * 1024;
        float4* sv = dsm + stg * 3072;
        float4* st = sv + 1024;
        int4*   sm = (int4*)(sv + 2048);
#pragma unroll
        for (int k = 0; k < 4; k++) {
            int f = tid + k * 256;
            int row = f >> 5, q = f & 31;
            int sidx = (row << 5) | (q ^ row);
            cpa16(sv + sidx, gv + f);
            cpa16(st + sidx, gt + f);
            cpa16(sm + sidx, gm + f);
        }
        cpa_commit();
    };

    issue(base, 0);
    if (n > 1) issue(base + 1, 1); else cpa_commit();

    for (int i = 0; i < n; i++) {
        int stg = i & 1;
        int chunk = base + i;
        float4* sv = dsm + stg * 3072;
        float4* st = sv + 1024;
        int4*   sm = (int4*)(sv + 2048);

        cpa_wait1();
        __syncthreads();

        int b = chunk / CC, c = chunk % CC;
#pragma unroll
        for (int j = 0; j < 4; j++) {
            int q = w * 4 + j;
            int sidx = (lane << 5) | (q ^ lane);
            float4 v4 = sv[sidx];
            float4 t4 = st[sidx];
            int4   mi = sm[sidx];

            unsigned bx = __ballot_sync(0xffffffffu, mi.x != 0);
            unsigned by = __ballot_sync(0xffffffffu, mi.y != 0);
            unsigned bz = __ballot_sync(0xffffffffu, mi.z != 0);
            unsigned bw = __ballot_sync(0xffffffffu, mi.w != 0);

            int agg0 = (b * DD + 4 * q) * CC + c;   // transposed aggregate index
            float4 oc;
            oc.x = do_ch(v4.x, t4.x, mi.x, bx, lmle, lmge, lane, agg0);
            oc.y = do_ch(v4.y, t4.y, mi.y, by, lmle, lmge, lane, agg0 + CC);
            oc.z = do_ch(v4.z, t4.z, mi.z, bz, lmle, lmge, lane, agg0 + 2 * CC);
            oc.w = do_ch(v4.w, t4.w, mi.w, bw, lmle, lmge, lane, agg0 + 3 * CC);
            sout[sidx] = oc;
        }
        __syncthreads();

        if (i + 2 < n) issue(base + i + 2, stg); else cpa_commit();

#pragma unroll
        for (int k = 0; k < 4; k++) {
            int f = tid + k * 256;
            int row = f >> 5, q = f & 31;
            __stcs(out + chunk * 1024 + f, sout[(row << 5) | (q ^ row)]);
        }
    }
}

// ---------------------------------------------------------------------------
// Pass BC: 512 blocks x 256 threads (R11 geometry). Block = 8 consecutive
// channels of one batch; warp w scans channel d0+w (R11's shuffle scans,
// coalesced transposed loads) and publishes per-chunk fixup states into a
// small padded smem tile [8][129]. After one barrier, threads remap so each
// repair access covers 8 consecutive d -> 4 wavefronts/instr instead of 32.
// Head/tail rows hold t_j from pass A -> repair is a pure out RMW.
// ---------------------------------------------------------------------------
__global__ __launch_bounds__(256) void passBC(const float* __restrict__ t,
                                              float* __restrict__ out) {
    __shared__ float4 sfH[NDB * SP];           // 16.5 KB
    __shared__ float4 sfT[NDB * SP];           // 16.5 KB
    __shared__ unsigned short sht[NDB * SP];   //  2 KB

    int tid = threadIdx.x;
    int lane = tid & 31, w = tid >> 5;          // 8 warps = 8 channels
    int gd = blockIdx.x * NDB + w;              // global (b*DD + d)
    int b = gd >> 7, d = gd & 127;
    int rowbase = gd * CC;

    // ---- coalesced aggregate loads: lane covers 4 consecutive chunks ----
    float2 af[4], ab[4];
#pragma unroll
    for (int j = 0; j < 4; j++) {
        af[j] = g_fwd2[rowbase + lane * 4 + j];
        ab[j] = g_bwd2[rowbase + lane * 4 + j];
    }
    unsigned hw = *(const unsigned*)(g_headb + rowbase + lane * 4);
    unsigned tw = *(const unsigned*)(g_tailb + rowbase + lane * 4);

    // ---- forward prefix scan (last obs over chunks < c) ----
    float fx = 0.f, ft = 0.f; int fh = 0;
#pragma unroll
    for (int j = 0; j < 4; j++)
        if (af[j].y != 0.f) { fx = af[j].x; ft = af[j].y; fh = 1; }
#pragma unroll
    for (int off = 1; off < 32; off <<= 1) {
        float px = __shfl_up_sync(0xffffffffu, fx, off);
        float pt = __shfl_up_sync(0xffffffffu, ft, off);
        int   ph = __shfl_up_sync(0xffffffffu, fh, off);
        if (lane >= off && !fh) { fx = px; ft = pt; fh = ph; }
    }
    float ex = __shfl_up_sync(0xffffffffu, fx, 1);
    float et = __shfl_up_sync(0xffffffffu, ft, 1);
    int   eh = __shfl_up_sync(0xffffffffu, fh, 1);
    float t0 = t[b * TT * DD + d];
    if (lane == 0 || !eh) { ex = 0.f; et = t0; }   // default seed

    // ---- backward suffix scan (next obs over chunks > c) ----
    float bx = 0.f, bt = 0.f; int bh = 0;
#pragma unroll
    for (int j = 3; j >= 0; j--)
        if (ab[j].y != 0.f) { bx = ab[j].x; bt = ab[j].y; bh = 1; }
#pragma unroll
    for (int off = 1; off < 32; off <<= 1) {
        float nx = __shfl_down_sync(0xffffffffu, bx, off);
        float nt = __shfl_down_sync(0xffffffffu, bt, off);
        int   nh = __shfl_down_sync(0xffffffffu, bh, off);
        if (lane < 32 - off && !bh) { bx = nx; bt = nt; bh = nh; }
    }
    float sx = __shfl_down_sync(0xffffffffu, bx, 1);
    float stt = __shfl_down_sync(0xffffffffu, bt, 1);
    int   sh = __shfl_down_sync(0xffffffffu, bh, 1);
    float tmax = t[(b * TT + TT - 1) * DD + d];
    if (lane == 31 || !sh) { sx = 0.f; stt = tmax; }  // default seed

    // Per-chunk exclusive suffix states (registers).
    float sufx[4], suft[4];
    {
        float cx = sx, ct = stt;
#pragma unroll
        for (int j = 3; j >= 0; j--) {
            sufx[j] = cx; suft[j] = ct;
            if (ab[j].y != 0.f) { cx = ab[j].x; ct = ab[j].y; }
        }
    }

    // ---- publish fixup states into smem [channel w][chunk c] ----
    float pxl = ex, ptl = et;      // exclusive forward state, walking j=0..3
#pragma unroll
    for (int j = 0; j < 4; j++) {
        int c = lane * 4 + j;
        int s = w * SP + c;
        int head = (hw >> (8 * j)) & 0xFF;
        int tail = (tw >> (8 * j)) & 0xFF;
        sht[s] = (unsigned short)(head | (tail << 8));

        if (head) {
            float xn, tn;
            if (ab[j].y != 0.f) { xn = ab[j].x; tn = ab[j].y; }
            else                { xn = sufx[j]; tn = suft[j]; }
            sfH[s] = make_float4(pxl, ptl, xn, tn);
        }
        if (tail) {
            // tail>0 implies the chunk has an observation -> lastInc = af[j]
            sfT[s] = make_float4(af[j].x, af[j].y, sufx[j], suft[j]);
        }
        if (af[j].y != 0.f) { pxl = af[j].x; ptl = af[j].y; }
    }
    __syncthreads();

    // ---- repair: warp w covers chunks [w*16, w*16+16); lane = cg*8 + dloc.
    // Each access: 4 chunks x 8 consecutive d -> 4 wavefronts.
    int dloc = lane & 7, cg = lane >> 3;
    int d2 = (blockIdx.x * NDB + dloc) & 127;
    int b2 = (blockIdx.x * NDB) >> 7;
#pragma unroll
    for (int k = 0; k < 4; k++) {
        int c = w * 16 + k * 4 + cg;
        int s = dloc * SP + c;
        unsigned ht = sht[s];
        int head = ht & 0xFF, tail = ht >> 8;
        int row0 = b2 * TT + c * CHUNK;

        if (head) {
            float4 f = sfH[s];             // (xl, tl, xn, tn)
            float den = f.w - f.y;
            float inv = (den != 0.f) ? __fdividef(1.f, den) : 0.f;
            for (int i = 0; i < head; i++) {
                int p = (row0 + i) * DD + d2;
                float tt = out[p];         // holds t_j from pass A
                out[p] = fmaf(f.x, f.w - tt, f.z * (tt - f.y)) * inv;
            }
        }
        if (tail) {
            float4 f = sfT[s];             // (xl, tl, xn, tn)
            float den = f.w - f.y;
            float inv = (den != 0.f) ? __fdividef(1.f, den) : 0.f;
            for (int i = CHUNK - tail; i < CHUNK; i++) {
                int p = (row0 + i) * DD + d2;
                float tt = out[p];
                out[p] = fmaf(f.x, f.w - tt, f.z * (tt - f.y)) * inv;
            }
        }
    }
}

// ---------------------------------------------------------------------------
extern "C" void kernel_launch(void* const* d_in, const int* in_sizes, int n_in,
                              void* d_out, int out_size) {
    const float4* v4 = (const float4*)d_in[0];
    const float4* t4 = (const float4*)d_in[1];
    const int4*   m4 = (const int4*)d_in[2];
    const float*  t  = (const float*)d_in[1];
    float4* out4 = (float4*)d_out;
    float*  out  = (float*)d_out;

    const int smemA = 7168 * (int)sizeof(float4);   // 112 KB
    cudaFuncSetAttribute(passA, cudaFuncAttributeMaxDynamicSharedMemorySize, smemA);

    passA<<<GRID_A, 256, smemA>>>(v4, t4, m4, out4);
    passBC<<<(BB * DD) / NDB, 256>>>(t, out);
}

// round 17
// speedup vs baseline: 1.2364x; 1.2364x over previous
#include <cuda_runtime.h>
#include <cstdint>

// Problem constants (fixed by the reference).
#define BB 32
#define TT 4096
#define DD 128
#define CHUNK 32
#define CC (TT / CHUNK)        // 128 chunks per batch
#define NCH (BB * CC)          // 4096 chunks
#define NAGG (NCH * DD)        // 524288 (chunk, channel) slots

#define GRID_A 296             // 2 blocks/SM
#define KPB 14                 // max chunks per block

// Scratch (static device memory — no allocations). Transposed layout
// [(b*DD+d)*CC + c] so pass BC's scan loads are coalesced. has-flag in .y
// (y == 0 => no observation; real times are > 0, cumsum of dt >= 0.1).
__device__ float2 g_fwd2[NAGG];            // per-chunk last-obs  (x, t|0)  4 MB
__device__ float2 g_bwd2[NAGG];            // per-chunk first-obs (x, t|0)  4 MB
__device__ unsigned char g_headb[NAGG];    // head length (rows before 1st obs)
__device__ unsigned char g_tailb[NAGG];    // tail length (rows after last obs)

// ---------------------------------------------------------------------------
// cp.async helpers
// ---------------------------------------------------------------------------
__device__ __forceinline__ void cpa16(void* dst_smem, const void* src) {
    unsigned d = (unsigned)__cvta_generic_to_shared(dst_smem);
    asm volatile("cp.async.cg.shared.global [%0], [%1], 16;" :: "r"(d), "l"(src));
}
__device__ __forceinline__ void cpa_commit() {
    asm volatile("cp.async.commit_group;");
}
__device__ __forceinline__ void cpa_wait1() {
    asm volatile("cp.async.wait_group 1;" ::: "memory");
}

// ---------------------------------------------------------------------------
// Per-channel worker: ballot-derived last/next observation indices, shuffle
// gather, branchless interpolation. Lane 31 / lane 0 emit chunk aggregates.
// Head/tail rows (no obs on one side within the chunk) get 0 here and are
// repaired by pass BC.
// ---------------------------------------------------------------------------
__device__ __forceinline__ float do_ch(float vj, float tj, int mch,
                                       unsigned bits, unsigned lmle, unsigned lmge,
                                       int lane, int agg) {
    int li = 31 - __clz(bits & lmle);        // last obs <= row, or -1
    int ni = __clz(__brev(bits & lmge));     // first obs >= row, or 32
    float xl = __shfl_sync(0xffffffffu, vj, li);   // idx taken mod 32 by HW
    float tl = __shfl_sync(0xffffffffu, tj, li);
    float xn = __shfl_sync(0xffffffffu, vj, ni);
    float tn = __shfl_sync(0xffffffffu, tj, ni);

    if (lane == 31) {
        g_fwd2[agg] = make_float2(xl, li >= 0 ? tl : 0.f);
        g_tailb[agg] = (unsigned char)(li < 0 ? 0 : 31 - li);
    }
    if (lane == 0) {
        g_bwd2[agg] = make_float2(xn, ni < 32 ? tn : 0.f);
        g_headb[agg] = (unsigned char)ni;    // 0..32 (32 = empty chunk)
    }

    float itp = __fdividef(fmaf(xl, tn - tj, xn * (tj - tl)), tn - tl);
    bool interior = (li >= 0) && (ni < 32);  // head/tail rows fixed by pass BC
    return mch ? vj : (interior ? itp : 0.f);
}

// ---------------------------------------------------------------------------
// Pass A: persistent double-buffered cp.async pipeline. Dyn smem 112 KB,
// 2 blocks/SM. Chunks are GRID-STRIDED across blocks (chunk = bid + i*GRID_A)
// so the resident blocks advance through memory as one coherent front
// (DRAM row-buffer / L2 locality), instead of 296 disjoint streams.
// ---------------------------------------------------------------------------
__global__ __launch_bounds__(256) void passA(const float4* __restrict__ v,
                                             const float4* __restrict__ t,
                                             const int4* __restrict__ m,
                                             float4* __restrict__ out) {
    extern __shared__ float4 dsm[];
    float4* sout = dsm + 6144;

    int tid = threadIdx.x;
    int bid = blockIdx.x;
    // number of chunks this block owns under striding
    int n = (NCH - 1 - bid) / GRID_A + 1;    // bid < GRID_A <= NCH: n >= 1

    int lane = tid & 31, w = tid >> 5;
    unsigned lmle, lmge;
    asm("mov.u32 %0, %%lanemask_le;" : "=r"(lmle));
    asm("mov.u32 %0, %%lanemask_ge;" : "=r"(lmge));

    auto issue = [&](int chunk, int stg) {
        const float4* gv = v + chunk * 1024;
        const float4* gt = t + chunk * 1024;
        const int4*   gm = m + chunk * 1024;
        float4* sv = dsm + stg * 3072;
        float4* st = sv + 1024;
        int4*   sm = (int4*)(sv + 2048);
#pragma unroll
        for (int k = 0; k < 4; k++) {
            int f = tid + k * 256;
            int row = f >> 5, q = f & 31;
            int sidx = (row << 5) | (q ^ row);
            cpa16(sv + sidx, gv + f);
            cpa16(st + sidx, gt + f);
            cpa16(sm + sidx, gm + f);
        }
        cpa_commit();
    };

    issue(bid, 0);
    if (n > 1) issue(bid + GRID_A, 1); else cpa_commit();

    for (int i = 0; i < n; i++) {
        int stg = i & 1;
        int chunk = bid + i * GRID_A;
        float4* sv = dsm + stg * 3072;
        float4* st = sv + 1024;
        int4*   sm = (int4*)(sv + 2048);

        cpa_wait1();
        __syncthreads();

        int b = chunk / CC, c = chunk % CC;
#pragma unroll
        for (int j = 0; j < 4; j++) {
            int q = w * 4 + j;
            int sidx = (lane << 5) | (q ^ lane);
            float4 v4 = sv[sidx];
            float4 t4 = st[sidx];
            int4   mi = sm[sidx];

            unsigned bx = __ballot_sync(0xffffffffu, mi.x != 0);
            unsigned by = __ballot_sync(0xffffffffu, mi.y != 0);
            unsigned bz = __ballot_sync(0xffffffffu, mi.z != 0);
            unsigned bw = __ballot_sync(0xffffffffu, mi.w != 0);

            int agg0 = (b * DD + 4 * q) * CC + c;   // transposed aggregate index
            float4 oc;
            oc.x = do_ch(v4.x, t4.x, mi.x, bx, lmle, lmge, lane, agg0);
            oc.y = do_ch(v4.y, t4.y, mi.y, by, lmle, lmge, lane, agg0 + CC);
            oc.z = do_ch(v4.z, t4.z, mi.z, bz, lmle, lmge, lane, agg0 + 2 * CC);
            oc.w = do_ch(v4.w, t4.w, mi.w, bw, lmle, lmge, lane, agg0 + 3 * CC);
            sout[sidx] = oc;
        }
        __syncthreads();

        if (i + 2 < n) issue(bid + (i + 2) * GRID_A, stg); else cpa_commit();

#pragma unroll
        for (int k = 0; k < 4; k++) {
            int f = tid + k * 256;
            int row = f >> 5, q = f & 31;
            __stcs(out + chunk * 1024 + f, sout[(row << 5) | (q ^ row)]);
        }
    }
}

// ---------------------------------------------------------------------------
// Pass BC (fused, R11-proven): one warp per (batch, channel). Lane covers 4
// consecutive chunks. Forward prefix scan (last obs) AND backward suffix
// scan (next obs) in the same warp -> exclusive incoming states live in
// registers only. Then each lane repairs its chunks' head/tail rows directly.
// ---------------------------------------------------------------------------
__global__ __launch_bounds__(256) void passBC(const float* __restrict__ t,
                                              float* __restrict__ out) {
    int gw = (blockIdx.x * 256 + threadIdx.x) >> 5;   // [0, BB*DD)
    int lane = threadIdx.x & 31;
    int b = gw >> 7, d = gw & 127;
    int rowbase = (b * DD + d) * CC;

    // Coalesced aggregate loads: lane reads 4 consecutive chunks.
    float2 af[4], ab[4];
#pragma unroll
    for (int j = 0; j < 4; j++) {
        af[j] = g_fwd2[rowbase + lane * 4 + j];
        ab[j] = g_bwd2[rowbase + lane * 4 + j];
    }
    unsigned hw = *(const unsigned*)(g_headb + rowbase + lane * 4);
    unsigned tw = *(const unsigned*)(g_tailb + rowbase + lane * 4);

    // ---- forward prefix scan (last obs over chunks < c) ----
    float fx = 0.f, ft = 0.f; int fh = 0;
#pragma unroll
    for (int j = 0; j < 4; j++)
        if (af[j].y != 0.f) { fx = af[j].x; ft = af[j].y; fh = 1; }
#pragma unroll
    for (int off = 1; off < 32; off <<= 1) {
        float px = __shfl_up_sync(0xffffffffu, fx, off);
        float pt = __shfl_up_sync(0xffffffffu, ft, off);
        int   ph = __shfl_up_sync(0xffffffffu, fh, off);
        if (lane >= off && !fh) { fx = px; ft = pt; fh = ph; }
    }
    float ex = __shfl_up_sync(0xffffffffu, fx, 1);
    float et = __shfl_up_sync(0xffffffffu, ft, 1);
    int   eh = __shfl_up_sync(0xffffffffu, fh, 1);
    float t0 = t[b * TT * DD + d];
    if (lane == 0 || !eh) { ex = 0.f; et = t0; }   // default seed

    // ---- backward suffix scan (next obs over chunks > c) ----
    float bx = 0.f, bt = 0.f; int bh = 0;
#pragma unroll
    for (int j = 3; j >= 0; j--)
        if (ab[j].y != 0.f) { bx = ab[j].x; bt = ab[j].y; bh = 1; }
#pragma unroll
    for (int off = 1; off < 32; off <<= 1) {
        float nx = __shfl_down_sync(0xffffffffu, bx, off);
        float nt = __shfl_down_sync(0xffffffffu, bt, off);
        int   nh = __shfl_down_sync(0xffffffffu, bh, off);
        if (lane < 32 - off && !bh) { bx = nx; bt = nt; bh = nh; }
    }
    float sx = __shfl_down_sync(0xffffffffu, bx, 1);
    float stt = __shfl_down_sync(0xffffffffu, bt, 1);
    int   sh = __shfl_down_sync(0xffffffffu, bh, 1);
    float tmax = t[(b * TT + TT - 1) * DD + d];
    if (lane == 31 || !sh) { sx = 0.f; stt = tmax; }  // default seed

    // Per-chunk exclusive suffix states (registers).
    float sufx[4], suft[4];
    {
        float cx = sx, ct = stt;
#pragma unroll
        for (int j = 3; j >= 0; j--) {
            sufx[j] = cx; suft[j] = ct;
            if (ab[j].y != 0.f) { cx = ab[j].x; ct = ab[j].y; }
        }
    }

    // ---- fixup: repair head/tail rows of each of the lane's 4 chunks ----
    float pxl = ex, ptl = et;      // exclusive forward state, walking j=0..3
#pragma unroll
    for (int j = 0; j < 4; j++) {
        int c = lane * 4 + j;
        int head = (hw >> (8 * j)) & 0xFF;
        int tail = (tw >> (8 * j)) & 0xFF;
        int row0 = b * TT + c * CHUNK;

        if (head) {
            float xn, tn;
            if (ab[j].y != 0.f) { xn = ab[j].x; tn = ab[j].y; }
            else                { xn = sufx[j]; tn = suft[j]; }
            float den = tn - ptl;
            float inv = (den != 0.f) ? __fdividef(1.f, den) : 0.f;
            for (int i = 0; i < head; i++) {
                float tt = t[(row0 + i) * DD + d];
                out[(row0 + i) * DD + d] = fmaf(pxl, tn - tt, xn * (tt - ptl)) * inv;
            }
        }
        if (tail) {
            float xl = af[j].x, tl = af[j].y;   // tail>0 implies obs in chunk
            float den = suft[j] - tl;
            float inv = (den != 0.f) ? __fdividef(1.f, den) : 0.f;
            for (int i = CHUNK - tail; i < CHUNK; i++) {
                float tt = t[(row0 + i) * DD + d];
                out[(row0 + i) * DD + d] = fmaf(xl, suft[j] - tt, sufx[j] * (tt - tl)) * inv;
            }
        }
        if (af[j].y != 0.f) { pxl = af[j].x; ptl = af[j].y; }
    }
}

// ---------------------------------------------------------------------------
extern "C" void kernel_launch(void* const* d_in, const int* in_sizes, int n_in,
                              void* d_out, int out_size) {
    const float4* v4 = (const float4*)d_in[0];
    const float4* t4 = (const float4*)d_in[1];
    const int4*   m4 = (const int4*)d_in[2];
    const float*  t  = (const float*)d_in[1];
    float4* out4 = (float4*)d_out;
    float*  out  = (float*)d_out;

    const int smemA = 7168 * (int)sizeof(float4);   // 112 KB
    cudaFuncSetAttribute(passA, cudaFuncAttributeMaxDynamicSharedMemorySize, smemA);

    passA<<<GRID_A, 256, smemA>>>(v4, t4, m4, out4);
    passBC<<<(BB * DD * 32) / 256, 256>>>(t, out);
}